// round 11
// baseline (speedup 1.0000x reference)
#include <cuda_runtime.h>
#include <cuda_fp16.h>
#include <cstdint>

// GRU decoder, H=4096, T=2048. Persistent single kernel + software grid barrier.
// R2: fp16 weight scratch -> L2-resident.   R6: batched loads + fast gates.
// R9: 9 warps' weights pinned in SMEM -> DRAM ~0%.
// R10: fp16 h in smem -> L1 traffic halved.                       [19.13 ms]
// R11: HFMA2 chunk-accumulated dot products (fused fp16 MACs, chunk of 8
//      -> fp32 once). Halves fma-pipe instruction count; h unpack eliminated.

#define HDIM 4096
#define IN_DIM 400
#define OROWS 401
#define NOUT 400
#define WARPS_PER_BLOCK 28
#define NTHREADS (WARPS_PER_BLOCK * 32)
#define PINNED_WARPS 9

#define SMEM_H_BYTES (HDIM * 2)                                  // 8192 (fp16 h)
#define PIN_HALVES (PINNED_WARPS * 3 * HDIM)                     // 110592 halves
#define SMEM_TOTAL (SMEM_H_BYTES + PIN_HALVES * 2)               // 229376 B

__device__ __half g_whh_h[(size_t)3 * HDIM * HDIM];   // 100.7 MB fp16 W_hh
__device__ __half g_wout_h[(size_t)OROWS * HDIM];     // 3.3 MB fp16 W_out
__device__ float g_h[2][HDIM];                        // double-buffered hidden state
__device__ float g_gx[3 * HDIM];                      // W_ih @ relu(x) + b_ih
__device__ unsigned g_cnt;
__device__ unsigned g_gen;

__device__ __forceinline__ float warp_sum(float v) {
#pragma unroll
    for (int o = 16; o; o >>= 1) v += __shfl_xor_sync(0xffffffffu, v, o);
    return v;
}

// Sense-reversing grid barrier; all blocks co-resident (grid == #SMs, 1 blk/SM).
__device__ __forceinline__ void grid_sync() {
    __syncthreads();
    if (threadIdx.x == 0) {
        __threadfence();
        unsigned gen = *(volatile unsigned*)&g_gen;
        unsigned nblk = gridDim.x;
        if (atomicAdd(&g_cnt, 1u) == nblk - 1u) {
            atomicExch(&g_cnt, 0u);
            __threadfence();
            atomicAdd(&g_gen, 1u);
        } else {
            while (*(volatile unsigned*)&g_gen == gen) { __nanosleep(32); }
        }
        __threadfence();
    }
    __syncthreads();
}

__device__ __forceinline__ float fast_sigmoid(float x) {
    float e;
    asm("ex2.approx.f32 %0, %1;" : "=f"(e) : "f"(-1.4426950408889634f * x));
    float r;
    asm("rcp.approx.f32 %0, %1;" : "=f"(r) : "f"(1.0f + e));
    return r;
}
__device__ __forceinline__ float fast_tanh(float x) {
    float r;
    asm("tanh.approx.f32 %0, %1;" : "=f"(r) : "f"(x));
    return r;
}

// fp16 chunk dot: 8 products (4 HFMA2, fused; each lane sums 4), fp32 out.
// acc.x/acc.y updated separately by caller.
__device__ __forceinline__ float2 dot8_h2(uint4 w, uint4 h) {
    __half2 p = __hmul2(*(const __half2*)&w.x, *(const __half2*)&h.x);
    p = __hfma2(*(const __half2*)&w.y, *(const __half2*)&h.y, p);
    p = __hfma2(*(const __half2*)&w.z, *(const __half2*)&h.z, p);
    p = __hfma2(*(const __half2*)&w.w, *(const __half2*)&h.w, p);
    return __half22float2(p);
}

// fp32-h variant for the final Stage B (h from global, fp32)
__device__ __forceinline__ float dot8f(uint4 u, float2 h0, float2 h1,
                                       float2 h2, float2 h3) {
    float2 p; float s0 = 0.f, s1 = 0.f;
    p = __half22float2(*(const __half2*)&u.x); s0 += p.x * h0.x; s1 += p.y * h0.y;
    p = __half22float2(*(const __half2*)&u.y); s0 += p.x * h1.x; s1 += p.y * h1.y;
    p = __half22float2(*(const __half2*)&u.z); s0 += p.x * h2.x; s1 += p.y * h2.y;
    p = __half22float2(*(const __half2*)&u.w); s0 += p.x * h3.x; s1 += p.y * h3.y;
    return s0 + s1;
}

__global__ void __launch_bounds__(NTHREADS, 1)
decoder_persistent_kernel(const float* __restrict__ start,
                          const float* __restrict__ enc,
                          const float* __restrict__ W_ih,
                          const float* __restrict__ W_hh,
                          const float* __restrict__ b_ih,
                          const float* __restrict__ b_hh,
                          const float* __restrict__ W_out,
                          const float* __restrict__ b_out,
                          const int*   __restrict__ maxlen_ptr,
                          float* __restrict__ out)
{
    extern __shared__ char smem_dyn[];
    __half* h_sh  = (__half*)smem_dyn;                      // 8 KB fp16 h
    __half* pin_w = (__half*)(smem_dyn + SMEM_H_BYTES);     // 216 KB pinned W

    const int lane   = threadIdx.x & 31;
    const int warp   = threadIdx.x >> 5;
    const int gwarp  = blockIdx.x * WARPS_PER_BLOCK + warp;
    const int gwarps = gridDim.x * WARPS_PER_BLOCK;
    const int gtid    = blockIdx.x * NTHREADS + threadIdx.x;
    const int gthreads = gridDim.x * NTHREADS;
    const int T = maxlen_ptr ? *maxlen_ptr : 2048;

    // ---- convert W_hh, W_out to fp16 scratch (every launch; deterministic) ----
    {
        const size_t total = (size_t)3 * HDIM * HDIM;
        for (size_t idx = (size_t)gtid * 4; idx < total; idx += (size_t)gthreads * 4) {
            float4 v = *(const float4*)(W_hh + idx);
            __half2* dst = (__half2*)(g_whh_h + idx);
            dst[0] = __floats2half2_rn(v.x, v.y);
            dst[1] = __floats2half2_rn(v.z, v.w);
        }
        const size_t ototal = (size_t)OROWS * HDIM;
        for (size_t idx = (size_t)gtid * 4; idx < ototal; idx += (size_t)gthreads * 4) {
            float4 v = *(const float4*)(W_out + idx);
            __half2* dst = (__half2*)(g_wout_h + idx);
            dst[0] = __floats2half2_rn(v.x, v.y);
            dst[1] = __floats2half2_rn(v.z, v.w);
        }
    }

    // ---- fill pinned smem weights for warps 0..PINNED_WARPS-1 (once) ----
    for (int idx = threadIdx.x * 4; idx < PIN_HALVES; idx += NTHREADS * 4) {
        int w   = idx / (3 * HDIM);
        int rem = idx - w * 3 * HDIM;
        int g   = rem / HDIM;
        int col = rem - g * HDIM;
        int row = blockIdx.x * WARPS_PER_BLOCK + w;
        if (row < HDIM) {
            float4 v = *(const float4*)(W_hh + ((size_t)(g * HDIM + row)) * HDIM + col);
            __half2* dst = (__half2*)(pin_w + idx);
            dst[0] = __floats2half2_rn(v.x, v.y);
            dst[1] = __floats2half2_rn(v.z, v.w);
        }
    }

    // ---- init: h0 = encoder_hidden ----
    for (int idx = gtid; idx < HDIM; idx += gthreads)
        g_h[0][idx] = enc[idx];

    // ---- gx = W_ih @ relu(start) + b_ih (once per launch, fp32) ----
    for (int r = gwarp; r < 3 * HDIM; r += gwarps) {
        const float* wr = W_ih + (size_t)r * IN_DIM;
        float acc = 0.f;
        for (int k = lane; k < IN_DIM; k += 32) {
            float x = start[k];
            x = x > 0.f ? x : 0.f;
            acc += wr[k] * x;
        }
        acc = warp_sum(acc);
        if (lane == 0) g_gx[r] = acc + b_ih[r];
    }
    grid_sync();

    // Stage-B row mapping: spread 401 W_out rows evenly across all SMs
    int spread = gwarps / OROWS;
    if (spread < 1) spread = 1;
    int brow = -1;
    if ((gwarp % spread) == 0 && (gwarp / spread) < OROWS) brow = gwarp / spread;

    const int myrow = (gwarp < HDIM) ? gwarp : -1;

    // hoist per-row constants out of the time loop
    float c_br = 0.f, c_bz = 0.f, c_bn = 0.f, c_gr = 0.f, c_gz = 0.f, c_gn = 0.f;
    if (myrow >= 0) {
        c_br = b_hh[myrow];
        c_bz = b_hh[myrow + HDIM];
        c_bn = b_hh[myrow + 2 * HDIM];
        c_gr = g_gx[myrow];
        c_gz = g_gx[myrow + HDIM];
        c_gn = g_gx[myrow + 2 * HDIM];
    }
    const float c_bo = (brow >= 0) ? b_out[brow] : 0.f;

    const bool pinned = (warp < PINNED_WARPS);

    // row-dot triple: fp16 HFMA2 chunks, dual fp32 accumulators per stream
    auto row_dots = [&](const uint4* __restrict__ w0, const uint4* __restrict__ w1,
                        const uint4* __restrict__ w2,
                        float& a0, float& a1, float& a2) {
        const uint4* hh = (const uint4*)h_sh;    // 512 chunks of 8 halves
        float b0 = 0.f, b1 = 0.f, b2 = 0.f;
        float x0 = 0.f, x1 = 0.f, x2 = 0.f;
#pragma unroll 8
        for (int k = lane; k < HDIM / 8; k += 32) {   // 16 iterations
            uint4 u0 = w0[k];
            uint4 u1 = w1[k];
            uint4 u2 = w2[k];
            uint4 hu = hh[k];
            float2 f0 = dot8_h2(u0, hu);
            float2 f1 = dot8_h2(u1, hu);
            float2 f2 = dot8_h2(u2, hu);
            x0 += f0.x; b0 += f0.y;
            x1 += f1.x; b1 += f1.y;
            x2 += f2.x; b2 += f2.y;
        }
        a0 = x0 + b0; a1 = x1 + b1; a2 = x2 + b2;
    };

    // ---- main recurrence ----
    for (int t = 0; t < T; t++) {
        const float* __restrict__ hc = g_h[t & 1];
        float* __restrict__ hn = g_h[(t + 1) & 1];

        // exact fp32 h_old for the recurrent z*h term (issued early; L2 hit)
        float h_old = (myrow >= 0) ? hc[myrow] : 0.f;

        // stage h_cur into shared memory as fp16 (8 halves per thread)
        {
            const float4* src = (const float4*)hc;
            uint4* dst = (uint4*)h_sh;
            for (int idx = threadIdx.x; idx < HDIM / 8; idx += NTHREADS) {
                float4 a = src[2 * idx];
                float4 b = src[2 * idx + 1];
                uint4 o;
                *(__half2*)&o.x = __floats2half2_rn(a.x, a.y);
                *(__half2*)&o.y = __floats2half2_rn(a.z, a.w);
                *(__half2*)&o.z = __floats2half2_rn(b.x, b.y);
                *(__half2*)&o.w = __floats2half2_rn(b.z, b.w);
                dst[idx] = o;
            }
        }
        __syncthreads();

        // Stage A: one warp per output i
        if (myrow >= 0) {
            float a0, a1, a2;
            if (pinned) {
                const __half* sw = pin_w + (size_t)warp * 3 * HDIM;
                row_dots((const uint4*)sw,
                         (const uint4*)(sw + HDIM),
                         (const uint4*)(sw + 2 * HDIM), a0, a1, a2);
            } else {
                row_dots((const uint4*)(g_whh_h + (size_t)myrow * HDIM),
                         (const uint4*)(g_whh_h + ((size_t)myrow + HDIM) * HDIM),
                         (const uint4*)(g_whh_h + ((size_t)myrow + 2 * HDIM) * HDIM),
                         a0, a1, a2);
            }
            a0 = warp_sum(a0);
            a1 = warp_sum(a1);
            a2 = warp_sum(a2);
            float r = fast_sigmoid(c_gr + a0 + c_br);
            float z = fast_sigmoid(c_gz + a1 + c_bz);
            float n = fast_tanh(c_gn + r * (a2 + c_bn));
            if (lane == 0) {
                hn[myrow] = (1.f - z) * n + z * h_old;
            }
        }

        // Stage B (deferred, for step t-1): h_new(t-1) == h_sh; pre-barrier.
        if (t > 0 && brow >= 0) {
            const uint4* wr = (const uint4*)(g_wout_h + (size_t)brow * HDIM);
            const uint4* hh = (const uint4*)h_sh;
            float acc = 0.f, accb = 0.f;
#pragma unroll 4
            for (int k = lane; k < HDIM / 8; k += 32) {
                float2 f = dot8_h2(wr[k], hh[k]);
                acc += f.x; accb += f.y;
            }
            acc = warp_sum(acc + accb);
            if (lane == 0) {
                float o = acc + c_bo;
                int tt = t - 1;
                if (brow < NOUT)
                    out[(size_t)tt * NOUT + brow] = fast_tanh(o);
                else
                    out[(size_t)T * NOUT + tt] = fast_sigmoid(o);
            }
        }

        grid_sync();   // h_new(t) globally visible
    }

    // ---- final Stage B for step T-1 (fp32 h from global) ----
    if (brow >= 0) {
        const float* hf = g_h[T & 1];
        const uint4* wr = (const uint4*)(g_wout_h + (size_t)brow * HDIM);
        float acc = 0.f;
#pragma unroll 4
        for (int k = lane; k < HDIM / 8; k += 32) {
            uint4 u = wr[k];
            const float4* hp = (const float4*)(hf + k * 8);
            float4 ha = hp[0], hb = hp[1];
            acc += dot8f(u, make_float2(ha.x, ha.y), make_float2(ha.z, ha.w),
                            make_float2(hb.x, hb.y), make_float2(hb.z, hb.w));
        }
        acc = warp_sum(acc);
        if (lane == 0) {
            float o = acc + c_bo;
            int tt = T - 1;
            if (brow < NOUT)
                out[(size_t)tt * NOUT + brow] = fast_tanh(o);
            else
                out[(size_t)T * NOUT + tt] = fast_sigmoid(o);
        }
    }
}

extern "C" void kernel_launch(void* const* d_in, const int* in_sizes, int n_in,
                              void* d_out, int out_size) {
    (void)in_sizes; (void)out_size;

    int dev = 0;
    cudaGetDevice(&dev);
    int sm = 148;
    cudaDeviceGetAttribute(&sm, cudaDevAttrMultiProcessorCount, dev);
    if (sm < 1) sm = 148;
    if (sm > 512) sm = 512;

    cudaFuncSetAttribute(decoder_persistent_kernel,
                         cudaFuncAttributeMaxDynamicSharedMemorySize, SMEM_TOTAL);

    const float* start = (const float*)d_in[0];
    const float* enc   = (const float*)d_in[1];
    const float* W_ih  = (const float*)d_in[2];
    const float* W_hh  = (const float*)d_in[3];
    const float* b_ih  = (const float*)d_in[4];
    const float* b_hh  = (const float*)d_in[5];
    const float* W_out = (const float*)d_in[6];
    const float* b_out = (const float*)d_in[7];
    const int* maxlen  = (n_in > 8) ? (const int*)d_in[8] : nullptr;

    decoder_persistent_kernel<<<sm, NTHREADS, SMEM_TOTAL>>>(
        start, enc, W_ih, W_hh, b_ih, b_hh, W_out, b_out, maxlen, (float*)d_out);
}

// round 12
// speedup vs baseline: 1.1741x; 1.1741x over previous
#include <cuda_runtime.h>
#include <cuda_fp16.h>
#include <cstdint>

// GRU decoder, H=4096, T=2048. Persistent single kernel + software grid barrier.
// R2: fp16 weight scratch -> L2-resident.   R6: batched loads + fast gates.
// R9: 9 warps' weights pinned in SMEM -> DRAM ~0%.
// R10: fp16 h in smem -> L1 traffic halved.                       [19.13 ms]
// R11 lesson: HFMA2 chunk chains deepened dependencies -> reverted to R10 math.
// R12: Stage B moved to PINNED warps (they finish Stage A early, pure LDS).
//      Before: Stage-B warps did 48+16 LDG chunks vs 48 for peers -> stragglers
//      that the grid barrier waits on. Now per-warp global-load is balanced.

#define HDIM 4096
#define IN_DIM 400
#define OROWS 401
#define NOUT 400
#define WARPS_PER_BLOCK 28
#define NTHREADS (WARPS_PER_BLOCK * 32)
#define PINNED_WARPS 9

#define SMEM_H_BYTES (HDIM * 2)                                  // 8192 (fp16 h)
#define PIN_HALVES (PINNED_WARPS * 3 * HDIM)                     // 110592 halves
#define SMEM_TOTAL (SMEM_H_BYTES + PIN_HALVES * 2)               // 229376 B

__device__ __half g_whh_h[(size_t)3 * HDIM * HDIM];   // 100.7 MB fp16 W_hh
__device__ __half g_wout_h[(size_t)OROWS * HDIM];     // 3.3 MB fp16 W_out
__device__ float g_h[2][HDIM];                        // double-buffered hidden state
__device__ float g_gx[3 * HDIM];                      // W_ih @ relu(x) + b_ih
__device__ unsigned g_cnt;
__device__ unsigned g_gen;

__device__ __forceinline__ float warp_sum(float v) {
#pragma unroll
    for (int o = 16; o; o >>= 1) v += __shfl_xor_sync(0xffffffffu, v, o);
    return v;
}

// Sense-reversing grid barrier; all blocks co-resident (grid == #SMs, 1 blk/SM).
__device__ __forceinline__ void grid_sync() {
    __syncthreads();
    if (threadIdx.x == 0) {
        __threadfence();
        unsigned gen = *(volatile unsigned*)&g_gen;
        unsigned nblk = gridDim.x;
        if (atomicAdd(&g_cnt, 1u) == nblk - 1u) {
            atomicExch(&g_cnt, 0u);
            __threadfence();
            atomicAdd(&g_gen, 1u);
        } else {
            while (*(volatile unsigned*)&g_gen == gen) { __nanosleep(32); }
        }
        __threadfence();
    }
    __syncthreads();
}

__device__ __forceinline__ float fast_sigmoid(float x) {
    float e;
    asm("ex2.approx.f32 %0, %1;" : "=f"(e) : "f"(-1.4426950408889634f * x));
    float r;
    asm("rcp.approx.f32 %0, %1;" : "=f"(r) : "f"(1.0f + e));
    return r;
}
__device__ __forceinline__ float fast_tanh(float x) {
    float r;
    asm("tanh.approx.f32 %0, %1;" : "=f"(r) : "f"(x));
    return r;
}

// dot of 8 fp16 weights (uint4) with 8 fp32 h values given as 4 float2
__device__ __forceinline__ float dot8f(uint4 u, float2 h0, float2 h1,
                                       float2 h2, float2 h3) {
    float2 p; float s0 = 0.f, s1 = 0.f;
    p = __half22float2(*(const __half2*)&u.x); s0 += p.x * h0.x; s1 += p.y * h0.y;
    p = __half22float2(*(const __half2*)&u.y); s0 += p.x * h1.x; s1 += p.y * h1.y;
    p = __half22float2(*(const __half2*)&u.z); s0 += p.x * h2.x; s1 += p.y * h2.y;
    p = __half22float2(*(const __half2*)&u.w); s0 += p.x * h3.x; s1 += p.y * h3.y;
    return s0 + s1;
}

__global__ void __launch_bounds__(NTHREADS, 1)
decoder_persistent_kernel(const float* __restrict__ start,
                          const float* __restrict__ enc,
                          const float* __restrict__ W_ih,
                          const float* __restrict__ W_hh,
                          const float* __restrict__ b_ih,
                          const float* __restrict__ b_hh,
                          const float* __restrict__ W_out,
                          const float* __restrict__ b_out,
                          const int*   __restrict__ maxlen_ptr,
                          float* __restrict__ out)
{
    extern __shared__ char smem_dyn[];
    __half* h_sh  = (__half*)smem_dyn;                      // 8 KB fp16 h
    __half* pin_w = (__half*)(smem_dyn + SMEM_H_BYTES);     // 216 KB pinned W

    const int lane   = threadIdx.x & 31;
    const int warp   = threadIdx.x >> 5;
    const int gwarp  = blockIdx.x * WARPS_PER_BLOCK + warp;
    const int gwarps = gridDim.x * WARPS_PER_BLOCK;
    const int gtid    = blockIdx.x * NTHREADS + threadIdx.x;
    const int gthreads = gridDim.x * NTHREADS;
    const int T = maxlen_ptr ? *maxlen_ptr : 2048;

    // ---- convert W_hh, W_out to fp16 scratch (every launch; deterministic) ----
    {
        const size_t total = (size_t)3 * HDIM * HDIM;
        for (size_t idx = (size_t)gtid * 4; idx < total; idx += (size_t)gthreads * 4) {
            float4 v = *(const float4*)(W_hh + idx);
            __half2* dst = (__half2*)(g_whh_h + idx);
            dst[0] = __floats2half2_rn(v.x, v.y);
            dst[1] = __floats2half2_rn(v.z, v.w);
        }
        const size_t ototal = (size_t)OROWS * HDIM;
        for (size_t idx = (size_t)gtid * 4; idx < ototal; idx += (size_t)gthreads * 4) {
            float4 v = *(const float4*)(W_out + idx);
            __half2* dst = (__half2*)(g_wout_h + idx);
            dst[0] = __floats2half2_rn(v.x, v.y);
            dst[1] = __floats2half2_rn(v.z, v.w);
        }
    }

    // ---- fill pinned smem weights for warps 0..PINNED_WARPS-1 (once) ----
    for (int idx = threadIdx.x * 4; idx < PIN_HALVES; idx += NTHREADS * 4) {
        int w   = idx / (3 * HDIM);
        int rem = idx - w * 3 * HDIM;
        int g   = rem / HDIM;
        int col = rem - g * HDIM;
        int row = blockIdx.x * WARPS_PER_BLOCK + w;
        if (row < HDIM) {
            float4 v = *(const float4*)(W_hh + ((size_t)(g * HDIM + row)) * HDIM + col);
            __half2* dst = (__half2*)(pin_w + idx);
            dst[0] = __floats2half2_rn(v.x, v.y);
            dst[1] = __floats2half2_rn(v.z, v.w);
        }
    }

    // ---- init: h0 = encoder_hidden ----
    for (int idx = gtid; idx < HDIM; idx += gthreads)
        g_h[0][idx] = enc[idx];

    // ---- gx = W_ih @ relu(start) + b_ih (once per launch, fp32) ----
    for (int r = gwarp; r < 3 * HDIM; r += gwarps) {
        const float* wr = W_ih + (size_t)r * IN_DIM;
        float acc = 0.f;
        for (int k = lane; k < IN_DIM; k += 32) {
            float x = start[k];
            x = x > 0.f ? x : 0.f;
            acc += wr[k] * x;
        }
        acc = warp_sum(acc);
        if (lane == 0) g_gx[r] = acc + b_ih[r];
    }
    grid_sync();

    // Stage-B rows assigned to PINNED warps only (they have no LDG in Stage A).
    // pid in [0, 152*9); rows 0..400 spread with stride 3.
    int brow = -1;
    if (warp < PINNED_WARPS) {
        int pid = blockIdx.x * PINNED_WARPS + warp;
        if ((pid % 3) == 0 && (pid / 3) < OROWS) brow = pid / 3;
    }

    const int myrow = (gwarp < HDIM) ? gwarp : -1;

    // hoist per-row constants out of the time loop
    float c_br = 0.f, c_bz = 0.f, c_bn = 0.f, c_gr = 0.f, c_gz = 0.f, c_gn = 0.f;
    if (myrow >= 0) {
        c_br = b_hh[myrow];
        c_bz = b_hh[myrow + HDIM];
        c_bn = b_hh[myrow + 2 * HDIM];
        c_gr = g_gx[myrow];
        c_gz = g_gx[myrow + HDIM];
        c_gn = g_gx[myrow + 2 * HDIM];
    }
    const float c_bo = (brow >= 0) ? b_out[brow] : 0.f;

    const bool pinned = (warp < PINNED_WARPS);

    // row-dot triple over fp16 h in smem (h unpacked once, reused by 3 streams)
    auto row_dots = [&](const uint4* __restrict__ w0, const uint4* __restrict__ w1,
                        const uint4* __restrict__ w2,
                        float& a0, float& a1, float& a2) {
        const uint4* hh = (const uint4*)h_sh;    // 512 chunks of 8 halves
#pragma unroll 8
        for (int k = lane; k < HDIM / 8; k += 32) {   // 16 iterations
            uint4 u0 = w0[k];
            uint4 u1 = w1[k];
            uint4 u2 = w2[k];
            uint4 hu = hh[k];
            float2 h0 = __half22float2(*(const __half2*)&hu.x);
            float2 h1 = __half22float2(*(const __half2*)&hu.y);
            float2 h2 = __half22float2(*(const __half2*)&hu.z);
            float2 h3 = __half22float2(*(const __half2*)&hu.w);
            a0 += dot8f(u0, h0, h1, h2, h3);
            a1 += dot8f(u1, h0, h1, h2, h3);
            a2 += dot8f(u2, h0, h1, h2, h3);
        }
    };

    // ---- main recurrence ----
    for (int t = 0; t < T; t++) {
        const float* __restrict__ hc = g_h[t & 1];
        float* __restrict__ hn = g_h[(t + 1) & 1];

        // exact fp32 h_old for the recurrent z*h term (issued early; L2 hit)
        float h_old = (myrow >= 0) ? hc[myrow] : 0.f;

        // stage h_cur into shared memory as fp16 (8 halves per thread)
        {
            const float4* src = (const float4*)hc;
            uint4* dst = (uint4*)h_sh;
            for (int idx = threadIdx.x; idx < HDIM / 8; idx += NTHREADS) {
                float4 a = src[2 * idx];
                float4 b = src[2 * idx + 1];
                uint4 o;
                *(__half2*)&o.x = __floats2half2_rn(a.x, a.y);
                *(__half2*)&o.y = __floats2half2_rn(a.z, a.w);
                *(__half2*)&o.z = __floats2half2_rn(b.x, b.y);
                *(__half2*)&o.w = __floats2half2_rn(b.z, b.w);
                dst[idx] = o;
            }
        }
        __syncthreads();

        // Stage A: one warp per output i
        if (myrow >= 0) {
            float a0 = 0.f, a1 = 0.f, a2 = 0.f;
            if (pinned) {
                const __half* sw = pin_w + (size_t)warp * 3 * HDIM;
                row_dots((const uint4*)sw,
                         (const uint4*)(sw + HDIM),
                         (const uint4*)(sw + 2 * HDIM), a0, a1, a2);
            } else {
                row_dots((const uint4*)(g_whh_h + (size_t)myrow * HDIM),
                         (const uint4*)(g_whh_h + ((size_t)myrow + HDIM) * HDIM),
                         (const uint4*)(g_whh_h + ((size_t)myrow + 2 * HDIM) * HDIM),
                         a0, a1, a2);
            }
            a0 = warp_sum(a0);
            a1 = warp_sum(a1);
            a2 = warp_sum(a2);
            float r = fast_sigmoid(c_gr + a0 + c_br);
            float z = fast_sigmoid(c_gz + a1 + c_bz);
            float n = fast_tanh(c_gn + r * (a2 + c_bn));
            if (lane == 0) {
                hn[myrow] = (1.f - z) * n + z * h_old;
            }
        }

        // Stage B (deferred, for step t-1): pinned warps only; h from h_sh.
        if (t > 0 && brow >= 0) {
            const uint4* wr = (const uint4*)(g_wout_h + (size_t)brow * HDIM);
            const uint4* hh = (const uint4*)h_sh;
            float acc = 0.f;
#pragma unroll 8
            for (int k = lane; k < HDIM / 8; k += 32) {
                uint4 u = wr[k];
                uint4 hu = hh[k];
                float2 h0 = __half22float2(*(const __half2*)&hu.x);
                float2 h1 = __half22float2(*(const __half2*)&hu.y);
                float2 h2 = __half22float2(*(const __half2*)&hu.z);
                float2 h3 = __half22float2(*(const __half2*)&hu.w);
                acc += dot8f(u, h0, h1, h2, h3);
            }
            acc = warp_sum(acc);
            if (lane == 0) {
                float o = acc + c_bo;
                int tt = t - 1;
                if (brow < NOUT)
                    out[(size_t)tt * NOUT + brow] = fast_tanh(o);
                else
                    out[(size_t)T * NOUT + tt] = fast_sigmoid(o);
            }
        }

        grid_sync();   // h_new(t) globally visible
    }

    // ---- final Stage B for step T-1 (fp32 h from global) ----
    if (brow >= 0) {
        const float* hf = g_h[T & 1];
        const uint4* wr = (const uint4*)(g_wout_h + (size_t)brow * HDIM);
        float acc = 0.f;
#pragma unroll 4
        for (int k = lane; k < HDIM / 8; k += 32) {
            uint4 u = wr[k];
            const float4* hp = (const float4*)(hf + k * 8);
            float4 ha = hp[0], hb = hp[1];
            acc += dot8f(u, make_float2(ha.x, ha.y), make_float2(ha.z, ha.w),
                            make_float2(hb.x, hb.y), make_float2(hb.z, hb.w));
        }
        acc = warp_sum(acc);
        if (lane == 0) {
            float o = acc + c_bo;
            int tt = T - 1;
            if (brow < NOUT)
                out[(size_t)tt * NOUT + brow] = fast_tanh(o);
            else
                out[(size_t)T * NOUT + tt] = fast_sigmoid(o);
        }
    }
}

extern "C" void kernel_launch(void* const* d_in, const int* in_sizes, int n_in,
                              void* d_out, int out_size) {
    (void)in_sizes; (void)out_size;

    int dev = 0;
    cudaGetDevice(&dev);
    int sm = 148;
    cudaDeviceGetAttribute(&sm, cudaDevAttrMultiProcessorCount, dev);
    if (sm < 1) sm = 148;
    if (sm > 512) sm = 512;

    cudaFuncSetAttribute(decoder_persistent_kernel,
                         cudaFuncAttributeMaxDynamicSharedMemorySize, SMEM_TOTAL);

    const float* start = (const float*)d_in[0];
    const float* enc   = (const float*)d_in[1];
    const float* W_ih  = (const float*)d_in[2];
    const float* W_hh  = (const float*)d_in[3];
    const float* b_ih  = (const float*)d_in[4];
    const float* b_hh  = (const float*)d_in[5];
    const float* W_out = (const float*)d_in[6];
    const float* b_out = (const float*)d_in[7];
    const int* maxlen  = (n_in > 8) ? (const int*)d_in[8] : nullptr;

    decoder_persistent_kernel<<<sm, NTHREADS, SMEM_TOTAL>>>(
        start, enc, W_ih, W_hh, b_ih, b_hh, W_out, b_out, maxlen, (float*)d_out);
}

// round 13
// speedup vs baseline: 1.4252x; 1.2139x over previous
#include <cuda_runtime.h>
#include <cuda_fp16.h>
#include <cstdint>

// GRU decoder, H=4096, T=2048. Persistent single kernel + software grid barrier.
// R2: fp16 weight scratch -> L2-resident.   R6: batched loads + fast gates.
// R9: 9 warps' weights pinned in SMEM -> DRAM ~0%.
// R10: fp16 h in smem.  R12: Stage B on pinned warps (straggler fix). [18.15 ms]
// R11 lesson: HFMA2 *serial chunk chains* stall; this round uses FLAT HFMA2:
// R13: (a) two independent half2 accumulators per stream, flushed to fp32
//          every 4 iterations (8-deep chains, groups independent) ->
//          Stage-A fma ops ~640 -> ~310 per warp per step;
//      (b) h_new also stored fp16 in global -> staging is a raw 8 KB copy
//          (no per-step cvt), numerics identical to R12.

#define HDIM 4096
#define IN_DIM 400
#define OROWS 401
#define NOUT 400
#define WARPS_PER_BLOCK 28
#define NTHREADS (WARPS_PER_BLOCK * 32)
#define PINNED_WARPS 9

#define SMEM_H_BYTES (HDIM * 2)                                  // 8192 (fp16 h)
#define PIN_HALVES (PINNED_WARPS * 3 * HDIM)                     // 110592 halves
#define SMEM_TOTAL (SMEM_H_BYTES + PIN_HALVES * 2)               // 229376 B

__device__ __half g_whh_h[(size_t)3 * HDIM * HDIM];   // 100.7 MB fp16 W_hh
__device__ __half g_wout_h[(size_t)OROWS * HDIM];     // 3.3 MB fp16 W_out
__device__ float  g_h[2][HDIM];                       // fp32 hidden (recurrence)
__device__ __half g_h16[2][HDIM];                     // fp16 hidden (dot inputs)
__device__ float  g_gx[3 * HDIM];                     // W_ih @ relu(x) + b_ih
__device__ unsigned g_cnt;
__device__ unsigned g_gen;

__device__ __forceinline__ float warp_sum(float v) {
#pragma unroll
    for (int o = 16; o; o >>= 1) v += __shfl_xor_sync(0xffffffffu, v, o);
    return v;
}

// Sense-reversing grid barrier; all blocks co-resident (grid == #SMs, 1 blk/SM).
__device__ __forceinline__ void grid_sync() {
    __syncthreads();
    if (threadIdx.x == 0) {
        __threadfence();
        unsigned gen = *(volatile unsigned*)&g_gen;
        unsigned nblk = gridDim.x;
        if (atomicAdd(&g_cnt, 1u) == nblk - 1u) {
            atomicExch(&g_cnt, 0u);
            __threadfence();
            atomicAdd(&g_gen, 1u);
        } else {
            while (*(volatile unsigned*)&g_gen == gen) { __nanosleep(32); }
        }
        __threadfence();
    }
    __syncthreads();
}

__device__ __forceinline__ float fast_sigmoid(float x) {
    float e;
    asm("ex2.approx.f32 %0, %1;" : "=f"(e) : "f"(-1.4426950408889634f * x));
    float r;
    asm("rcp.approx.f32 %0, %1;" : "=f"(r) : "f"(1.0f + e));
    return r;
}
__device__ __forceinline__ float fast_tanh(float x) {
    float r;
    asm("tanh.approx.f32 %0, %1;" : "=f"(r) : "f"(x));
    return r;
}

// fp32-h variant for the final Stage B (h from global, fp32)
__device__ __forceinline__ float dot8f(uint4 u, float2 h0, float2 h1,
                                       float2 h2, float2 h3) {
    float2 p; float s0 = 0.f, s1 = 0.f;
    p = __half22float2(*(const __half2*)&u.x); s0 += p.x * h0.x; s1 += p.y * h0.y;
    p = __half22float2(*(const __half2*)&u.y); s0 += p.x * h1.x; s1 += p.y * h1.y;
    p = __half22float2(*(const __half2*)&u.z); s0 += p.x * h2.x; s1 += p.y * h2.y;
    p = __half22float2(*(const __half2*)&u.w); s0 += p.x * h3.x; s1 += p.y * h3.y;
    return s0 + s1;
}

__global__ void __launch_bounds__(NTHREADS, 1)
decoder_persistent_kernel(const float* __restrict__ start,
                          const float* __restrict__ enc,
                          const float* __restrict__ W_ih,
                          const float* __restrict__ W_hh,
                          const float* __restrict__ b_ih,
                          const float* __restrict__ b_hh,
                          const float* __restrict__ W_out,
                          const float* __restrict__ b_out,
                          const int*   __restrict__ maxlen_ptr,
                          float* __restrict__ out)
{
    extern __shared__ char smem_dyn[];
    __half* h_sh  = (__half*)smem_dyn;                      // 8 KB fp16 h
    __half* pin_w = (__half*)(smem_dyn + SMEM_H_BYTES);     // 216 KB pinned W

    const int lane   = threadIdx.x & 31;
    const int warp   = threadIdx.x >> 5;
    const int gwarp  = blockIdx.x * WARPS_PER_BLOCK + warp;
    const int gwarps = gridDim.x * WARPS_PER_BLOCK;
    const int gtid    = blockIdx.x * NTHREADS + threadIdx.x;
    const int gthreads = gridDim.x * NTHREADS;
    const int T = maxlen_ptr ? *maxlen_ptr : 2048;

    // ---- convert W_hh, W_out to fp16 scratch (every launch; deterministic) ----
    {
        const size_t total = (size_t)3 * HDIM * HDIM;
        for (size_t idx = (size_t)gtid * 4; idx < total; idx += (size_t)gthreads * 4) {
            float4 v = *(const float4*)(W_hh + idx);
            __half2* dst = (__half2*)(g_whh_h + idx);
            dst[0] = __floats2half2_rn(v.x, v.y);
            dst[1] = __floats2half2_rn(v.z, v.w);
        }
        const size_t ototal = (size_t)OROWS * HDIM;
        for (size_t idx = (size_t)gtid * 4; idx < ototal; idx += (size_t)gthreads * 4) {
            float4 v = *(const float4*)(W_out + idx);
            __half2* dst = (__half2*)(g_wout_h + idx);
            dst[0] = __floats2half2_rn(v.x, v.y);
            dst[1] = __floats2half2_rn(v.z, v.w);
        }
    }

    // ---- fill pinned smem weights for warps 0..PINNED_WARPS-1 (once) ----
    for (int idx = threadIdx.x * 4; idx < PIN_HALVES; idx += NTHREADS * 4) {
        int w   = idx / (3 * HDIM);
        int rem = idx - w * 3 * HDIM;
        int g   = rem / HDIM;
        int col = rem - g * HDIM;
        int row = blockIdx.x * WARPS_PER_BLOCK + w;
        if (row < HDIM) {
            float4 v = *(const float4*)(W_hh + ((size_t)(g * HDIM + row)) * HDIM + col);
            __half2* dst = (__half2*)(pin_w + idx);
            dst[0] = __floats2half2_rn(v.x, v.y);
            dst[1] = __floats2half2_rn(v.z, v.w);
        }
    }

    // ---- init: h0 = encoder_hidden (fp32 + fp16 copies) ----
    for (int idx = gtid; idx < HDIM; idx += gthreads) {
        float v = enc[idx];
        g_h[0][idx] = v;
        g_h16[0][idx] = __float2half_rn(v);
    }

    // ---- gx = W_ih @ relu(start) + b_ih (once per launch, fp32) ----
    for (int r = gwarp; r < 3 * HDIM; r += gwarps) {
        const float* wr = W_ih + (size_t)r * IN_DIM;
        float acc = 0.f;
        for (int k = lane; k < IN_DIM; k += 32) {
            float x = start[k];
            x = x > 0.f ? x : 0.f;
            acc += wr[k] * x;
        }
        acc = warp_sum(acc);
        if (lane == 0) g_gx[r] = acc + b_ih[r];
    }
    grid_sync();

    // Stage-B rows assigned to PINNED warps only (no LDG in their Stage A).
    int brow = -1;
    if (warp < PINNED_WARPS) {
        int pid = blockIdx.x * PINNED_WARPS + warp;
        if ((pid % 3) == 0 && (pid / 3) < OROWS) brow = pid / 3;
    }

    const int myrow = (gwarp < HDIM) ? gwarp : -1;

    // hoist per-row constants out of the time loop
    float c_br = 0.f, c_bz = 0.f, c_bn = 0.f, c_gr = 0.f, c_gz = 0.f, c_gn = 0.f;
    if (myrow >= 0) {
        c_br = b_hh[myrow];
        c_bz = b_hh[myrow + HDIM];
        c_bn = b_hh[myrow + 2 * HDIM];
        c_gr = g_gx[myrow];
        c_gz = g_gx[myrow + HDIM];
        c_gn = g_gx[myrow + 2 * HDIM];
    }
    const float c_bo = (brow >= 0) ? b_out[brow] : 0.f;

    const bool pinned = (warp < PINNED_WARPS);

    // Flat HFMA2 row-dot triple: per stream 2 independent half2 accumulators,
    // flushed to fp32 every 4 iterations (max 8 fp16-accumulated products per
    // half-lane -> quantization noise stays ~1e-4 absolute).
    auto row_dots = [&](const uint4* __restrict__ w0, const uint4* __restrict__ w1,
                        const uint4* __restrict__ w2,
                        float& a0, float& a1, float& a2) {
        const uint4* hh = (const uint4*)h_sh;    // 512 chunks of 8 halves
        a0 = 0.f; a1 = 0.f; a2 = 0.f;
        const __half2 z2 = __float2half2_rn(0.f);
#pragma unroll
        for (int g = 0; g < 4; g++) {
            __half2 A0 = z2, B0 = z2, A1 = z2, B1 = z2, A2 = z2, B2 = z2;
#pragma unroll
            for (int j = 0; j < 4; j++) {
                int k = lane + (g * 4 + j) * 32;
                uint4 u0 = w0[k];
                uint4 u1 = w1[k];
                uint4 u2 = w2[k];
                uint4 hu = hh[k];
                __half2 hx = *(const __half2*)&hu.x;
                __half2 hy = *(const __half2*)&hu.y;
                __half2 hz = *(const __half2*)&hu.z;
                __half2 hw = *(const __half2*)&hu.w;
                A0 = __hfma2(*(const __half2*)&u0.x, hx, A0);
                B0 = __hfma2(*(const __half2*)&u0.y, hy, B0);
                A0 = __hfma2(*(const __half2*)&u0.z, hz, A0);
                B0 = __hfma2(*(const __half2*)&u0.w, hw, B0);
                A1 = __hfma2(*(const __half2*)&u1.x, hx, A1);
                B1 = __hfma2(*(const __half2*)&u1.y, hy, B1);
                A1 = __hfma2(*(const __half2*)&u1.z, hz, A1);
                B1 = __hfma2(*(const __half2*)&u1.w, hw, B1);
                A2 = __hfma2(*(const __half2*)&u2.x, hx, A2);
                B2 = __hfma2(*(const __half2*)&u2.y, hy, B2);
                A2 = __hfma2(*(const __half2*)&u2.z, hz, A2);
                B2 = __hfma2(*(const __half2*)&u2.w, hw, B2);
            }
            float2 f0 = __half22float2(__hadd2(A0, B0));
            float2 f1 = __half22float2(__hadd2(A1, B1));
            float2 f2 = __half22float2(__hadd2(A2, B2));
            a0 += f0.x + f0.y;
            a1 += f1.x + f1.y;
            a2 += f2.x + f2.y;
        }
    };

    // ---- main recurrence ----
    for (int t = 0; t < T; t++) {
        const float*  __restrict__ hc   = g_h[t & 1];
        float*        __restrict__ hn   = g_h[(t + 1) & 1];
        const __half* __restrict__ hc16 = g_h16[t & 1];
        __half*       __restrict__ hn16 = g_h16[(t + 1) & 1];

        // exact fp32 h_old for the recurrent z*h term (issued early; L2 hit)
        float h_old = (myrow >= 0) ? hc[myrow] : 0.f;

        // stage fp16 h_cur into shared memory (raw 8 KB copy, no cvt)
        {
            const uint4* src = (const uint4*)hc16;
            uint4* dst = (uint4*)h_sh;
            for (int idx = threadIdx.x; idx < HDIM / 8; idx += NTHREADS)
                dst[idx] = src[idx];
        }
        __syncthreads();

        // Stage A: one warp per output i
        if (myrow >= 0) {
            float a0, a1, a2;
            if (pinned) {
                const __half* sw = pin_w + (size_t)warp * 3 * HDIM;
                row_dots((const uint4*)sw,
                         (const uint4*)(sw + HDIM),
                         (const uint4*)(sw + 2 * HDIM), a0, a1, a2);
            } else {
                row_dots((const uint4*)(g_whh_h + (size_t)myrow * HDIM),
                         (const uint4*)(g_whh_h + ((size_t)myrow + HDIM) * HDIM),
                         (const uint4*)(g_whh_h + ((size_t)myrow + 2 * HDIM) * HDIM),
                         a0, a1, a2);
            }
            a0 = warp_sum(a0);
            a1 = warp_sum(a1);
            a2 = warp_sum(a2);
            float r = fast_sigmoid(c_gr + a0 + c_br);
            float z = fast_sigmoid(c_gz + a1 + c_bz);
            float n = fast_tanh(c_gn + r * (a2 + c_bn));
            if (lane == 0) {
                float hv = (1.f - z) * n + z * h_old;
                hn[myrow] = hv;
                hn16[myrow] = __float2half_rn(hv);
            }
        }

        // Stage B (deferred, for step t-1): pinned warps only; h from h_sh.
        if (t > 0 && brow >= 0) {
            const uint4* wr = (const uint4*)(g_wout_h + (size_t)brow * HDIM);
            const uint4* hh = (const uint4*)h_sh;
            float acc = 0.f;
            const __half2 z2 = __float2half2_rn(0.f);
#pragma unroll
            for (int g = 0; g < 4; g++) {
                __half2 A = z2, B = z2;
#pragma unroll
                for (int j = 0; j < 4; j++) {
                    int k = lane + (g * 4 + j) * 32;
                    uint4 u = wr[k];
                    uint4 hu = hh[k];
                    A = __hfma2(*(const __half2*)&u.x, *(const __half2*)&hu.x, A);
                    B = __hfma2(*(const __half2*)&u.y, *(const __half2*)&hu.y, B);
                    A = __hfma2(*(const __half2*)&u.z, *(const __half2*)&hu.z, A);
                    B = __hfma2(*(const __half2*)&u.w, *(const __half2*)&hu.w, B);
                }
                float2 f = __half22float2(__hadd2(A, B));
                acc += f.x + f.y;
            }
            acc = warp_sum(acc);
            if (lane == 0) {
                float o = acc + c_bo;
                int tt = t - 1;
                if (brow < NOUT)
                    out[(size_t)tt * NOUT + brow] = fast_tanh(o);
                else
                    out[(size_t)T * NOUT + tt] = fast_sigmoid(o);
            }
        }

        grid_sync();   // h_new(t) globally visible
    }

    // ---- final Stage B for step T-1 (fp32 h from global) ----
    if (brow >= 0) {
        const float* hf = g_h[T & 1];
        const uint4* wr = (const uint4*)(g_wout_h + (size_t)brow * HDIM);
        float acc = 0.f;
#pragma unroll 4
        for (int k = lane; k < HDIM / 8; k += 32) {
            uint4 u = wr[k];
            const float4* hp = (const float4*)(hf + k * 8);
            float4 ha = hp[0], hb = hp[1];
            acc += dot8f(u, make_float2(ha.x, ha.y), make_float2(ha.z, ha.w),
                            make_float2(hb.x, hb.y), make_float2(hb.z, hb.w));
        }
        acc = warp_sum(acc);
        if (lane == 0) {
            float o = acc + c_bo;
            int tt = T - 1;
            if (brow < NOUT)
                out[(size_t)tt * NOUT + brow] = fast_tanh(o);
            else
                out[(size_t)T * NOUT + tt] = fast_sigmoid(o);
        }
    }
}

extern "C" void kernel_launch(void* const* d_in, const int* in_sizes, int n_in,
                              void* d_out, int out_size) {
    (void)in_sizes; (void)out_size;

    int dev = 0;
    cudaGetDevice(&dev);
    int sm = 148;
    cudaDeviceGetAttribute(&sm, cudaDevAttrMultiProcessorCount, dev);
    if (sm < 1) sm = 148;
    if (sm > 512) sm = 512;

    cudaFuncSetAttribute(decoder_persistent_kernel,
                         cudaFuncAttributeMaxDynamicSharedMemorySize, SMEM_TOTAL);

    const float* start = (const float*)d_in[0];
    const float* enc   = (const float*)d_in[1];
    const float* W_ih  = (const float*)d_in[2];
    const float* W_hh  = (const float*)d_in[3];
    const float* b_ih  = (const float*)d_in[4];
    const float* b_hh  = (const float*)d_in[5];
    const float* W_out = (const float*)d_in[6];
    const float* b_out = (const float*)d_in[7];
    const int* maxlen  = (n_in > 8) ? (const int*)d_in[8] : nullptr;

    decoder_persistent_kernel<<<sm, NTHREADS, SMEM_TOTAL>>>(
        start, enc, W_ih, W_hh, b_ih, b_hh, W_out, b_out, maxlen, (float*)d_out);
}